// round 4
// baseline (speedup 1.0000x reference)
#include <cuda_runtime.h>
#include <cstdint>

#define HDIM 1024
#define NCTA 128
#define NTHR 512

// Persistent cross-kernel state (allocation-free: __device__ globals).
__device__ unsigned g_counter;          // grid arrive counter (monotonic within a launch)
__device__ float g_hbuf[2][HDIM];       // double-buffered hidden state

__global__ void lstm_init_kernel() { g_counter = 0u; }

__device__ __forceinline__ unsigned ld_acquire_gpu(const unsigned* p) {
    unsigned v;
    asm volatile("ld.acquire.gpu.global.u32 %0, [%1];" : "=r"(v) : "l"(p) : "memory");
    return v;
}
__device__ __forceinline__ void red_release_gpu_add(unsigned* p, unsigned v) {
    asm volatile("red.release.gpu.global.add.u32 [%0], %1;" :: "l"(p), "r"(v) : "memory");
}
__device__ __forceinline__ float2 ldcg_f2(const float2* p) {
    float2 v;
    asm volatile("ld.global.cg.v2.f32 {%0,%1}, [%2];" : "=f"(v.x), "=f"(v.y) : "l"(p) : "memory");
    return v;
}
__device__ __forceinline__ float sigf(float x)  { return 1.0f / (1.0f + __expf(-x)); }
__device__ __forceinline__ float tanha(float x) { return 2.0f / (1.0f + __expf(-2.0f * x)) - 1.0f; }

// 128 CTAs x 512 threads. CTA b owns hidden indices j in [8b, 8b+8).
// Warp w (0..15) owns 2 gate rows r=2w, 2w+1 where r = gate*8 + jj,
// i.e. global row R = (r>>3)*1024 + 8b + (r&7). Each lane holds 64 W_hh
// weights in registers (2 rows x 32 cols, k = c*128 + lane*4 + d).
__global__ void __launch_bounds__(NTHR, 1)
lstm_kernel(const float* __restrict__ x,
            const float* __restrict__ W_ih,
            const float* __restrict__ W_hh,
            const float* __restrict__ b_ih,
            const float* __restrict__ b_hh,
            const int*   __restrict__ nn,
            float*       __restrict__ out)
{
    __shared__ float hsm[HDIM];
    __shared__ float gsm[32];

    const int tid = threadIdx.x;
    const int w   = tid >> 5;
    const int l   = tid & 31;
    const int b   = blockIdx.x;
    const int N   = *nn;

    const int r0 = 2 * w;
    const int r1 = 2 * w + 1;
    const int R0 = (r0 >> 3) * HDIM + b * 8 + (r0 & 7);
    const int R1 = (r1 >> 3) * HDIM + b * 8 + (r1 & 7);
    const int kb = l * 4;

    // Stage x into hsm (reused as h staging later).
    {
        float2 v = *(const float2*)(x + 2 * tid);
        *(float2*)(hsm + 2 * tid) = v;
    }

    // Pin this thread's W_hh weights in registers (coalesced float4 loads).
    float wA[32], wB[32];
    {
        const float4* pA = (const float4*)(W_hh + (size_t)R0 * HDIM + kb);
        const float4* pB = (const float4*)(W_hh + (size_t)R1 * HDIM + kb);
        #pragma unroll
        for (int c = 0; c < 8; c++) {
            float4 a = __ldg(pA + c * 32);   // +c*128 floats
            float4 q = __ldg(pB + c * 32);
            wA[4*c+0] = a.x; wA[4*c+1] = a.y; wA[4*c+2] = a.z; wA[4*c+3] = a.w;
            wB[4*c+0] = q.x; wB[4*c+1] = q.y; wB[4*c+2] = q.z; wB[4*c+3] = q.w;
        }
    }
    __syncthreads();   // x staged in hsm

    // x_gates = x @ W_ih^T + b_ih + b_hh for rows R0, R1 (stream W_ih once).
    float xgA, xgB;
    {
        float aA = 0.f, aB = 0.f;
        const float4* pA = (const float4*)(W_ih + (size_t)R0 * HDIM + kb);
        const float4* pB = (const float4*)(W_ih + (size_t)R1 * HDIM + kb);
        #pragma unroll
        for (int c = 0; c < 8; c++) {
            float4 hv = *(const float4*)(hsm + c * 128 + kb);
            float4 a  = __ldg(pA + c * 32);
            float4 q  = __ldg(pB + c * 32);
            aA = fmaf(a.x, hv.x, fmaf(a.y, hv.y, fmaf(a.z, hv.z, fmaf(a.w, hv.w, aA))));
            aB = fmaf(q.x, hv.x, fmaf(q.y, hv.y, fmaf(q.z, hv.z, fmaf(q.w, hv.w, aB))));
        }
        #pragma unroll
        for (int off = 16; off; off >>= 1) {
            aA += __shfl_xor_sync(0xffffffffu, aA, off);
            aB += __shfl_xor_sync(0xffffffffu, aB, off);
        }
        xgA = aA + b_ih[R0] + b_hh[R0];
        xgB = aB + b_ih[R1] + b_hh[R1];
    }

    float cstate = 0.f;   // cell state, owned by threads 0..7 (index jj = tid)

    // ---- step 0: h = 0 -> gates = x_gates ----
    if (l == 0) { gsm[r0] = xgA; gsm[r1] = xgB; }
    __syncthreads();
    if (tid < 8) {
        float yi = gsm[tid], yf = gsm[8 + tid], yg = gsm[16 + tid], yo = gsm[24 + tid];
        float ii = sigf(yi), ff = sigf(yf), gg = tanha(yg), oo = sigf(yo);
        float c  = fmaf(ff, cstate, ii * gg);
        cstate   = c;
        float h  = oo * tanha(c);
        int col  = b * 8 + tid;
        g_hbuf[1][col] = h;        // step 0 writes buf[(0+1)&1] = buf[1]
        out[col] = h;              // out row 0 = h_1
    }
    __syncthreads();
    if (tid == 0) red_release_gpu_add(&g_counter, 1u);

    // ---- steps 1..N-1 ----
    for (int s = 1; s < N; s++) {
        // Wait until all 128 CTAs published h_s.
        if (tid == 0) {
            const unsigned target = (unsigned)NCTA * (unsigned)s;
            while (ld_acquire_gpu(&g_counter) < target) { }
        }
        __syncthreads();

        // Stage h_s from L2 into shared (bypass stale L1 with .cg).
        {
            float2 hv = ldcg_f2(((const float2*)&g_hbuf[s & 1][0]) + tid);
            *(float2*)(hsm + 2 * tid) = hv;
        }
        __syncthreads();

        // Matvec: each warp computes 2 full gate rows from register weights.
        float aA = 0.f, aB = 0.f;
        #pragma unroll
        for (int c = 0; c < 8; c++) {
            float4 hv = *(const float4*)(hsm + c * 128 + kb);
            aA = fmaf(wA[4*c+0], hv.x, fmaf(wA[4*c+1], hv.y,
                 fmaf(wA[4*c+2], hv.z, fmaf(wA[4*c+3], hv.w, aA))));
            aB = fmaf(wB[4*c+0], hv.x, fmaf(wB[4*c+1], hv.y,
                 fmaf(wB[4*c+2], hv.z, fmaf(wB[4*c+3], hv.w, aB))));
        }
        #pragma unroll
        for (int off = 16; off; off >>= 1) {
            aA += __shfl_xor_sync(0xffffffffu, aA, off);
            aB += __shfl_xor_sync(0xffffffffu, aB, off);
        }
        if (l == 0) { gsm[r0] = aA + xgA; gsm[r1] = aB + xgB; }
        __syncthreads();

        // Gate nonlinearities + state update for this CTA's 8 hidden units.
        if (tid < 8) {
            float yi = gsm[tid], yf = gsm[8 + tid], yg = gsm[16 + tid], yo = gsm[24 + tid];
            float ii = sigf(yi), ff = sigf(yf), gg = tanha(yg), oo = sigf(yo);
            float c  = fmaf(ff, cstate, ii * gg);
            cstate   = c;
            float h  = oo * tanha(c);
            int col  = b * 8 + tid;
            g_hbuf[(s + 1) & 1][col] = h;
            out[(size_t)s * HDIM + col] = h;    // out row s = h_{s+1}
        }
        __syncthreads();
        if (tid == 0) red_release_gpu_add(&g_counter, 1u);
    }
}

extern "C" void kernel_launch(void* const* d_in, const int* in_sizes, int n_in,
                              void* d_out, int out_size) {
    const float* x    = (const float*)d_in[0];   // projected_representation [1,1024]
    const float* Wih  = (const float*)d_in[1];   // [4096,1024]
    const float* Whh  = (const float*)d_in[2];   // [4096,1024]
    const float* bih  = (const float*)d_in[3];   // [4096]
    const float* bhh  = (const float*)d_in[4];   // [4096]
    const int*   nn   = (const int*)d_in[5];     // num_nodes
    float* out = (float*)d_out;                  // [N,1024] fp32

    lstm_init_kernel<<<1, 1>>>();
    lstm_kernel<<<NCTA, NTHR>>>(x, Wih, Whh, bih, bhh, nn, out);
}